// round 2
// baseline (speedup 1.0000x reference)
#include <cuda_runtime.h>
#include <cstdint>

typedef unsigned long long u64;

#define TABLE_SIZE 524288
#define HMASK 524287u
#define PRIME_Y 2654435761u

// floor(16 * 1.3819^l), double precision, matches the JAX reference
__device__ constexpr int RES_A[16] = {16, 22, 30, 42, 58, 80, 111, 153, 212,
                                      294, 406, 561, 775, 1072, 1481, 2047};
// levels 0..4 staged in shared memory; sides 17,23,31,43,59
__device__ constexpr int LOFF[5] = {0, 289, 818, 1779, 3628};
#define TAB_ENTRIES 7109  // sum of sides^2 for levels 0..4

// ---------------- packed f32x2 helpers (sm_103a FFMA2 path) ----------------
__device__ __forceinline__ u64 ffma2(u64 a, u64 b, u64 c) {
    u64 d;
    asm("fma.rn.f32x2 %0, %1, %2, %3;" : "=l"(d) : "l"(a), "l"(b), "l"(c));
    return d;
}
__device__ __forceinline__ u64 splat2(float v) {
    u64 r; unsigned u = __float_as_uint(v);
    asm("mov.b64 %0, {%1, %2};" : "=l"(r) : "r"(u), "r"(u));
    return r;
}
__device__ __forceinline__ u64 pack2(float a, float b) {
    u64 r; unsigned ua = __float_as_uint(a), ub = __float_as_uint(b);
    asm("mov.b64 %0, {%1, %2};" : "=l"(r) : "r"(ua), "r"(ub));
    return r;
}
__device__ __forceinline__ float2 unpack2(u64 v) {
    unsigned a, b;
    asm("mov.b64 {%0, %1}, %2;" : "=r"(a), "=r"(b) : "l"(v));
    return make_float2(__uint_as_float(a), __uint_as_float(b));
}

struct G4 { float2 f00, f10, f01, f11; float wx, wy; };

__device__ __forceinline__ void corner_idx(float2 p, int res, bool hashed,
                                           unsigned& i00, unsigned& i10,
                                           unsigned& i01, unsigned& i11,
                                           float& wx, float& wy) {
    float fx = p.x * (float)res, fy = p.y * (float)res;
    float x0 = floorf(fx), y0 = floorf(fy);
    wx = fx - x0; wy = fy - y0;
    unsigned xi = (unsigned)x0, yi = (unsigned)y0;
    if (hashed) {
        unsigned t0 = yi * PRIME_Y, t1 = (yi + 1u) * PRIME_Y;
        i00 = (xi ^ t0) & HMASK; i10 = ((xi + 1u) ^ t0) & HMASK;
        i01 = (xi ^ t1) & HMASK; i11 = ((xi + 1u) ^ t1) & HMASK;
    } else {
        unsigned s = (unsigned)res + 1u;
        unsigned b = xi + yi * s;
        i00 = b; i10 = b + 1u; i01 = b + s; i11 = b + s + 1u;
    }
}

__device__ __forceinline__ float2 bilerp(const G4& g) {
    float u = 1.f - g.wx, v = 1.f - g.wy;
    float w00 = u * v, w10 = g.wx * v, w01 = u * g.wy, w11 = g.wx * g.wy;
    float f0 = g.f00.x * w00 + g.f10.x * w10 + g.f01.x * w01 + g.f11.x * w11;
    float f1 = g.f00.y * w00 + g.f10.y * w10 + g.f01.y * w01 + g.f11.y * w11;
    return make_float2(f0, f1);
}

// h[32] packed pairs over output neurons; accumulate two w1 rows (one level)
__device__ __forceinline__ void accum_row2(u64* h, const u64* r0, const u64* r1,
                                           float f0, float f1) {
    u64 e0 = splat2(f0), e1 = splat2(f1);
#pragma unroll
    for (int t = 0; t < 16; t++) {
        ulonglong2 a = ((const ulonglong2*)r0)[t];
        ulonglong2 b = ((const ulonglong2*)r1)[t];
        h[2 * t]     = ffma2(e0, a.x, h[2 * t]);
        h[2 * t + 1] = ffma2(e0, a.y, h[2 * t + 1]);
        h[2 * t]     = ffma2(e1, b.x, h[2 * t]);
        h[2 * t + 1] = ffma2(e1, b.y, h[2 * t + 1]);
    }
}

__global__ void __launch_bounds__(256, 2)
hashmlp_kernel(const float* __restrict__ x,
               const float* __restrict__ tables,
               const float* __restrict__ w1,
               const float* __restrict__ w2,
               const float* __restrict__ w3,
               float* __restrict__ out, int n) {
    extern __shared__ unsigned char sraw[];
    u64* w1s   = (u64*)sraw;               // 34*32 u64  (8704 B)
    u64* w2s   = w1s + 34 * 32;            // 64*32 u64  (16384 B)
    float* w3s = (float*)(w2s + 64 * 32);  // 192 floats (768 B)
    float2* tabs = (float2*)(w3s + 192);   // 7109 float2 (56872 B)

    const int tid = threadIdx.x;

    // ---- stage weights + coarse tables into SMEM ----
    {
        float* w1f = (float*)w1s;
        for (int t = tid; t < 34 * 64; t += 256) w1f[t] = w1[t];
        float* w2f = (float*)w2s;
        for (int t = tid; t < 64 * 64; t += 256) w2f[t] = w2[t];
        for (int t = tid; t < 192; t += 256) w3s[t] = w3[t];
#pragma unroll
        for (int l = 0; l < 5; l++) {
            const float2* src = (const float2*)tables + (size_t)l * TABLE_SIZE;
            const int sz = (RES_A[l] + 1) * (RES_A[l] + 1);
            for (int t = tid; t < sz; t += 256) tabs[LOFF[l] + t] = src[t];
        }
    }
    __syncthreads();

    const int i = blockIdx.x * 256 + tid;
    if (i >= n) return;
    const float2 p = ((const float2*)x)[i];

    // ---- layer 1, fused with encoding: h1[j] accumulated as enc produced ----
    u64 h[32];
#pragma unroll
    for (int j = 0; j < 32; j++) h[j] = 0ull;

    accum_row2(h, w1s + 0, w1s + 32, p.x, p.y); // raw x,y inputs (rows 0,1)

    // levels 0..4: gather from SMEM-staged tables
#pragma unroll
    for (int l = 0; l < 5; l++) {
        unsigned a, b, c, d; G4 g;
        corner_idx(p, RES_A[l], false, a, b, c, d, g.wx, g.wy);
        const float2* tb = tabs + LOFF[l];
        g.f00 = tb[a]; g.f10 = tb[b]; g.f01 = tb[c]; g.f11 = tb[d];
        float2 f = bilerp(g);
        accum_row2(h, w1s + (2 + 2 * l) * 32, w1s + (3 + 2 * l) * 32, f.x, f.y);
    }

    // levels 5..15: gather from global (L2-resident), prefetch one level ahead
    G4 g;
    {
        unsigned a, b, c, d;
        corner_idx(p, RES_A[5], false, a, b, c, d, g.wx, g.wy);
        const float2* tb = (const float2*)tables + (size_t)5 * TABLE_SIZE;
        g.f00 = tb[a]; g.f10 = tb[b]; g.f01 = tb[c]; g.f11 = tb[d];
    }
#pragma unroll
    for (int l = 5; l < 16; l++) {
        G4 cur = g;
        if (l < 15) {
            unsigned a, b, c, d;
            corner_idx(p, RES_A[l + 1], (l + 1) >= 12, a, b, c, d, g.wx, g.wy);
            const float2* tb = (const float2*)tables + (size_t)(l + 1) * TABLE_SIZE;
            g.f00 = tb[a]; g.f10 = tb[b]; g.f01 = tb[c]; g.f11 = tb[d];
        }
        float2 f = bilerp(cur);
        accum_row2(h, w1s + (2 + 2 * l) * 32, w1s + (3 + 2 * l) * 32, f.x, f.y);
    }

    // relu layer 1
#pragma unroll
    for (int j = 0; j < 32; j++) {
        float2 t = unpack2(h[j]);
        h[j] = pack2(fmaxf(t.x, 0.f), fmaxf(t.y, 0.f));
    }

    // ---- layer 2 (chunked 16 outputs at a time) + fused relu + layer 3 ----
    float o0 = 0.f, o1 = 0.f, o2 = 0.f;
#pragma unroll
    for (int c = 0; c < 4; c++) {
        u64 acc[8];
#pragma unroll
        for (int q = 0; q < 8; q++) acc[q] = 0ull;
#pragma unroll
        for (int j2 = 0; j2 < 32; j2++) {
            float2 hp = unpack2(h[j2]);
            u64 a0 = splat2(hp.x), a1 = splat2(hp.y);
            const u64* r0 = w2s + (2 * j2) * 32 + c * 8;
            const u64* r1 = w2s + (2 * j2 + 1) * 32 + c * 8;
#pragma unroll
            for (int t = 0; t < 4; t++) {
                ulonglong2 wa = ((const ulonglong2*)r0)[t];
                acc[2 * t]     = ffma2(a0, wa.x, acc[2 * t]);
                acc[2 * t + 1] = ffma2(a0, wa.y, acc[2 * t + 1]);
            }
#pragma unroll
            for (int t = 0; t < 4; t++) {
                ulonglong2 wb = ((const ulonglong2*)r1)[t];
                acc[2 * t]     = ffma2(a1, wb.x, acc[2 * t]);
                acc[2 * t + 1] = ffma2(a1, wb.y, acc[2 * t + 1]);
            }
        }
#pragma unroll
        for (int q = 0; q < 8; q++) {
            float2 t = unpack2(acc[q]);
            float ha = fmaxf(t.x, 0.f), hb = fmaxf(t.y, 0.f);
            int i0 = (c * 16 + 2 * q) * 3;
            o0 += ha * w3s[i0 + 0] + hb * w3s[i0 + 3];
            o1 += ha * w3s[i0 + 1] + hb * w3s[i0 + 4];
            o2 += ha * w3s[i0 + 2] + hb * w3s[i0 + 5];
        }
    }

    const size_t off = (size_t)i * 3;
    out[off + 0] = o0; out[off + 1] = o1; out[off + 2] = o2;
}

extern "C" void kernel_launch(void* const* d_in, const int* in_sizes, int n_in,
                              void* d_out, int out_size) {
    const float* x      = (const float*)d_in[0];
    const float* tables = (const float*)d_in[1];
    const float* w1     = (const float*)d_in[2];
    const float* w2     = (const float*)d_in[3];
    const float* w3     = (const float*)d_in[4];
    float* out = (float*)d_out;

    const int n = in_sizes[0] / 2; // x is [N,2]
    const int smem_bytes = (34 * 32 + 64 * 32) * 8 + 192 * 4 + TAB_ENTRIES * 8; // 82728

    cudaFuncSetAttribute(hashmlp_kernel,
                         cudaFuncAttributeMaxDynamicSharedMemorySize, smem_bytes);

    const int blocks = (n + 255) / 256;
    hashmlp_kernel<<<blocks, 256, smem_bytes>>>(x, tables, w1, w2, w3, out, n);
}

// round 5
// speedup vs baseline: 1.0849x; 1.0849x over previous
#include <cuda_runtime.h>
#include <cstdint>

typedef unsigned long long u64;

#define TABLE_SIZE 524288
#define HMASK 524287u
#define PRIME_Y 2654435761u
#define NPTS_MAX (1 << 21)
#define NBINS 16384  // 128x128 Morton tiles

// floor(16 * 1.3819^l), double precision, matches the JAX reference
__device__ constexpr int RES_A[16] = {16, 22, 30, 42, 58, 80, 111, 153, 212,
                                      294, 406, 561, 775, 1072, 1481, 2047};
// levels 0..4 staged in shared memory; sides 17,23,31,43,59
__device__ constexpr int LOFF[5] = {0, 289, 818, 1779, 3628};
#define TAB_ENTRIES 7109  // sum of sides^2 for levels 0..4

// ---------------- sort scratch (static device globals; no allocs) ----------
__device__ int g_hist[NBINS];
__device__ int g_off[NBINS];
__device__ float2 g_sx[NPTS_MAX];
__device__ int g_sidx[NPTS_MAX];

// ---------------- packed f32x2 helpers (sm_103a FFMA2 path) ----------------
__device__ __forceinline__ u64 ffma2(u64 a, u64 b, u64 c) {
    u64 d;
    asm("fma.rn.f32x2 %0, %1, %2, %3;" : "=l"(d) : "l"(a), "l"(b), "l"(c));
    return d;
}
__device__ __forceinline__ u64 splat2(float v) {
    u64 r; unsigned u = __float_as_uint(v);
    asm("mov.b64 %0, {%1, %2};" : "=l"(r) : "r"(u), "r"(u));
    return r;
}
__device__ __forceinline__ u64 pack2(float a, float b) {
    u64 r; unsigned ua = __float_as_uint(a), ub = __float_as_uint(b);
    asm("mov.b64 %0, {%1, %2};" : "=l"(r) : "r"(ua), "r"(ub));
    return r;
}
__device__ __forceinline__ float2 unpack2(u64 v) {
    unsigned a, b;
    asm("mov.b64 {%0, %1}, %2;" : "=r"(a), "=r"(b) : "l"(v));
    return make_float2(__uint_as_float(a), __uint_as_float(b));
}

// ---------------- Morton key ----------------
__device__ __forceinline__ unsigned spread8(unsigned v) {
    v &= 0xFFu;
    v = (v | (v << 4)) & 0x0F0Fu;
    v = (v | (v << 2)) & 0x3333u;
    v = (v | (v << 1)) & 0x5555u;
    return v;
}
__device__ __forceinline__ int morton_key(float2 p) {
    unsigned cx = (unsigned)(p.x * 128.0f);
    unsigned cy = (unsigned)(p.y * 128.0f);
    cx = cx > 127u ? 127u : cx;
    cy = cy > 127u ? 127u : cy;
    return (int)(spread8(cx) | (spread8(cy) << 1));
}

// ---------------- sort kernels ----------------
__global__ void zero_hist_k() {
    int i = blockIdx.x * blockDim.x + threadIdx.x;
    if (i < NBINS) g_hist[i] = 0;
}

__global__ void hist_k(const float2* __restrict__ x, int n) {
    int i = blockIdx.x * blockDim.x + threadIdx.x;
    if (i < n) atomicAdd(&g_hist[morton_key(x[i])], 1);
}

__global__ void scan_k() {  // 1 block, 1024 threads; 16 bins per thread
    __shared__ int tot[1024];
    const int t = threadIdx.x;
    const int base = t * 16;
    int loc[16];
    int s = 0;
#pragma unroll
    for (int k = 0; k < 16; k++) { loc[k] = g_hist[base + k]; s += loc[k]; }
    tot[t] = s;
    __syncthreads();
    // Hillis-Steele inclusive scan
    for (int off = 1; off < 1024; off <<= 1) {
        int v = (t >= off) ? tot[t - off] : 0;
        __syncthreads();
        tot[t] += v;
        __syncthreads();
    }
    int run = tot[t] - s;  // exclusive prefix for this thread's chunk
#pragma unroll
    for (int k = 0; k < 16; k++) { g_off[base + k] = run; run += loc[k]; }
}

__global__ void scatter_k(const float2* __restrict__ x, int n) {
    int i = blockIdx.x * blockDim.x + threadIdx.x;
    if (i < n) {
        float2 p = x[i];
        int pos = atomicAdd(&g_off[morton_key(p)], 1);
        g_sx[pos] = p;
        g_sidx[pos] = i;
    }
}

// ---------------- main fused encode+MLP kernel ----------------
struct G4 { float2 f00, f10, f01, f11; float wx, wy; };

__device__ __forceinline__ void corner_idx(float2 p, int res, bool hashed,
                                           unsigned& i00, unsigned& i10,
                                           unsigned& i01, unsigned& i11,
                                           float& wx, float& wy) {
    float fx = p.x * (float)res, fy = p.y * (float)res;
    float x0 = floorf(fx), y0 = floorf(fy);
    wx = fx - x0; wy = fy - y0;
    unsigned xi = (unsigned)x0, yi = (unsigned)y0;
    if (hashed) {
        unsigned t0 = yi * PRIME_Y, t1 = (yi + 1u) * PRIME_Y;
        i00 = (xi ^ t0) & HMASK; i10 = ((xi + 1u) ^ t0) & HMASK;
        i01 = (xi ^ t1) & HMASK; i11 = ((xi + 1u) ^ t1) & HMASK;
    } else {
        unsigned s = (unsigned)res + 1u;
        unsigned b = xi + yi * s;
        i00 = b; i10 = b + 1u; i01 = b + s; i11 = b + s + 1u;
    }
}

__device__ __forceinline__ float2 bilerp(const G4& g) {
    float u = 1.f - g.wx, v = 1.f - g.wy;
    float w00 = u * v, w10 = g.wx * v, w01 = u * g.wy, w11 = g.wx * g.wy;
    float f0 = g.f00.x * w00 + g.f10.x * w10 + g.f01.x * w01 + g.f11.x * w11;
    float f1 = g.f00.y * w00 + g.f10.y * w10 + g.f01.y * w01 + g.f11.y * w11;
    return make_float2(f0, f1);
}

__device__ __forceinline__ void accum_row2(u64* h, const u64* r0, const u64* r1,
                                           float f0, float f1) {
    u64 e0 = splat2(f0), e1 = splat2(f1);
#pragma unroll
    for (int t = 0; t < 16; t++) {
        ulonglong2 a = ((const ulonglong2*)r0)[t];
        ulonglong2 b = ((const ulonglong2*)r1)[t];
        h[2 * t]     = ffma2(e0, a.x, h[2 * t]);
        h[2 * t + 1] = ffma2(e0, a.y, h[2 * t + 1]);
        h[2 * t]     = ffma2(e1, b.x, h[2 * t]);
        h[2 * t + 1] = ffma2(e1, b.y, h[2 * t + 1]);
    }
}

__global__ void __launch_bounds__(256, 2)
hashmlp_kernel(const float* __restrict__ tables,
               const float* __restrict__ w1,
               const float* __restrict__ w2,
               const float* __restrict__ w3,
               float* __restrict__ out, int n) {
    extern __shared__ unsigned char sraw[];
    u64* w1s   = (u64*)sraw;               // 34*32 u64  (8704 B)
    u64* w2s   = w1s + 34 * 32;            // 64*32 u64  (16384 B)
    float* w3s = (float*)(w2s + 64 * 32);  // 192 floats (768 B)
    float2* tabs = (float2*)(w3s + 192);   // 7109 float2 (56872 B)

    const int tid = threadIdx.x;

    {
        float* w1f = (float*)w1s;
        for (int t = tid; t < 34 * 64; t += 256) w1f[t] = w1[t];
        float* w2f = (float*)w2s;
        for (int t = tid; t < 64 * 64; t += 256) w2f[t] = w2[t];
        for (int t = tid; t < 192; t += 256) w3s[t] = w3[t];
#pragma unroll
        for (int l = 0; l < 5; l++) {
            const float2* src = (const float2*)tables + (size_t)l * TABLE_SIZE;
            const int sz = (RES_A[l] + 1) * (RES_A[l] + 1);
            for (int t = tid; t < sz; t += 256) tabs[LOFF[l] + t] = src[t];
        }
    }
    __syncthreads();

    const int i = blockIdx.x * 256 + tid;
    if (i >= n) return;
    const float2 p = g_sx[i];          // spatially sorted point
    const int oi = g_sidx[i];          // original index for output

    u64 h[32];
#pragma unroll
    for (int j = 0; j < 32; j++) h[j] = 0ull;

    accum_row2(h, w1s + 0, w1s + 32, p.x, p.y);

    // levels 0..4: SMEM tables
#pragma unroll
    for (int l = 0; l < 5; l++) {
        unsigned a, b, c, d; G4 g;
        corner_idx(p, RES_A[l], false, a, b, c, d, g.wx, g.wy);
        const float2* tb = tabs + LOFF[l];
        g.f00 = tb[a]; g.f10 = tb[b]; g.f01 = tb[c]; g.f11 = tb[d];
        float2 f = bilerp(g);
        accum_row2(h, w1s + (2 + 2 * l) * 32, w1s + (3 + 2 * l) * 32, f.x, f.y);
    }

    // levels 5..15: global (L2/L1-resident after sorting), prefetch 1 ahead
    G4 g;
    {
        unsigned a, b, c, d;
        corner_idx(p, RES_A[5], false, a, b, c, d, g.wx, g.wy);
        const float2* tb = (const float2*)tables + (size_t)5 * TABLE_SIZE;
        g.f00 = tb[a]; g.f10 = tb[b]; g.f01 = tb[c]; g.f11 = tb[d];
    }
#pragma unroll
    for (int l = 5; l < 16; l++) {
        G4 cur = g;
        if (l < 15) {
            unsigned a, b, c, d;
            corner_idx(p, RES_A[l + 1], (l + 1) >= 12, a, b, c, d, g.wx, g.wy);
            const float2* tb = (const float2*)tables + (size_t)(l + 1) * TABLE_SIZE;
            g.f00 = tb[a]; g.f10 = tb[b]; g.f01 = tb[c]; g.f11 = tb[d];
        }
        float2 f = bilerp(cur);
        accum_row2(h, w1s + (2 + 2 * l) * 32, w1s + (3 + 2 * l) * 32, f.x, f.y);
    }

#pragma unroll
    for (int j = 0; j < 32; j++) {
        float2 t = unpack2(h[j]);
        h[j] = pack2(fmaxf(t.x, 0.f), fmaxf(t.y, 0.f));
    }

    float o0 = 0.f, o1 = 0.f, o2 = 0.f;
#pragma unroll
    for (int c = 0; c < 4; c++) {
        u64 acc[8];
#pragma unroll
        for (int q = 0; q < 8; q++) acc[q] = 0ull;
#pragma unroll
        for (int j2 = 0; j2 < 32; j2++) {
            float2 hp = unpack2(h[j2]);
            u64 a0 = splat2(hp.x), a1 = splat2(hp.y);
            const u64* r0 = w2s + (2 * j2) * 32 + c * 8;
            const u64* r1 = w2s + (2 * j2 + 1) * 32 + c * 8;
#pragma unroll
            for (int t = 0; t < 4; t++) {
                ulonglong2 wa = ((const ulonglong2*)r0)[t];
                acc[2 * t]     = ffma2(a0, wa.x, acc[2 * t]);
                acc[2 * t + 1] = ffma2(a0, wa.y, acc[2 * t + 1]);
            }
#pragma unroll
            for (int t = 0; t < 4; t++) {
                ulonglong2 wb = ((const ulonglong2*)r1)[t];
                acc[2 * t]     = ffma2(a1, wb.x, acc[2 * t]);
                acc[2 * t + 1] = ffma2(a1, wb.y, acc[2 * t + 1]);
            }
        }
#pragma unroll
        for (int q = 0; q < 8; q++) {
            float2 t = unpack2(acc[q]);
            float ha = fmaxf(t.x, 0.f), hb = fmaxf(t.y, 0.f);
            int i0 = (c * 16 + 2 * q) * 3;
            o0 += ha * w3s[i0 + 0] + hb * w3s[i0 + 3];
            o1 += ha * w3s[i0 + 1] + hb * w3s[i0 + 4];
            o2 += ha * w3s[i0 + 2] + hb * w3s[i0 + 5];
        }
    }

    const size_t off = (size_t)oi * 3;
    out[off + 0] = o0; out[off + 1] = o1; out[off + 2] = o2;
}

extern "C" void kernel_launch(void* const* d_in, const int* in_sizes, int n_in,
                              void* d_out, int out_size) {
    const float* x      = (const float*)d_in[0];
    const float* tables = (const float*)d_in[1];
    const float* w1     = (const float*)d_in[2];
    const float* w2     = (const float*)d_in[3];
    const float* w3     = (const float*)d_in[4];
    float* out = (float*)d_out;

    const int n = in_sizes[0] / 2;  // x is [N,2]
    const float2* x2 = (const float2*)x;

    // ---- spatial counting sort (Morton 14-bit) ----
    zero_hist_k<<<NBINS / 256, 256>>>();
    hist_k<<<(n + 255) / 256, 256>>>(x2, n);
    scan_k<<<1, 1024>>>();
    scatter_k<<<(n + 255) / 256, 256>>>(x2, n);

    // ---- fused encode + MLP ----
    const int smem_bytes = (34 * 32 + 64 * 32) * 8 + 192 * 4 + TAB_ENTRIES * 8;
    cudaFuncSetAttribute(hashmlp_kernel,
                         cudaFuncAttributeMaxDynamicSharedMemorySize, smem_bytes);
    hashmlp_kernel<<<(n + 255) / 256, 256, smem_bytes>>>(tables, w1, w2, w3,
                                                         out, n);
}

// round 8
// speedup vs baseline: 2.4055x; 2.2173x over previous
#include <cuda_runtime.h>
#include <cuda_bf16.h>
#include <cstdint>

typedef unsigned long long u64;
typedef unsigned int u32;
typedef unsigned short u16;

#define TABLE_SIZE 524288
#define HMASK 524287u
#define PRIME_Y 2654435761u
#define NPTS_MAX (1 << 21)
#define NBINS 16384

__device__ constexpr int RES_A[16] = {16, 22, 30, 42, 58, 80, 111, 153, 212,
                                      294, 406, 561, 775, 1072, 1481, 2047};

// ---------------- sort scratch ----------------
__device__ int g_hist[NBINS];
__device__ int g_off[NBINS];
__device__ float2 g_sx[NPTS_MAX];
__device__ int g_sidx[NPTS_MAX];

// ---------------- Morton sort kernels ----------------
__device__ __forceinline__ unsigned spread8(unsigned v) {
    v &= 0xFFu;
    v = (v | (v << 4)) & 0x0F0Fu;
    v = (v | (v << 2)) & 0x3333u;
    v = (v | (v << 1)) & 0x5555u;
    return v;
}
__device__ __forceinline__ int morton_key(float2 p) {
    unsigned cx = (unsigned)(p.x * 128.0f);
    unsigned cy = (unsigned)(p.y * 128.0f);
    cx = cx > 127u ? 127u : cx;
    cy = cy > 127u ? 127u : cy;
    return (int)(spread8(cx) | (spread8(cy) << 1));
}
__global__ void zero_hist_k() {
    int i = blockIdx.x * blockDim.x + threadIdx.x;
    if (i < NBINS) g_hist[i] = 0;
}
__global__ void hist_k(const float2* __restrict__ x, int n) {
    int i = blockIdx.x * blockDim.x + threadIdx.x;
    if (i < n) atomicAdd(&g_hist[morton_key(x[i])], 1);
}
__global__ void scan_k() {
    __shared__ int tot[1024];
    const int t = threadIdx.x;
    const int base = t * 16;
    int loc[16];
    int s = 0;
#pragma unroll
    for (int k = 0; k < 16; k++) { loc[k] = g_hist[base + k]; s += loc[k]; }
    tot[t] = s;
    __syncthreads();
    for (int off = 1; off < 1024; off <<= 1) {
        int v = (t >= off) ? tot[t - off] : 0;
        __syncthreads();
        tot[t] += v;
        __syncthreads();
    }
    int run = tot[t] - s;
#pragma unroll
    for (int k = 0; k < 16; k++) { g_off[base + k] = run; run += loc[k]; }
}
__global__ void scatter_k(const float2* __restrict__ x, int n) {
    int i = blockIdx.x * blockDim.x + threadIdx.x;
    if (i < n) {
        float2 p = x[i];
        int pos = atomicAdd(&g_off[morton_key(p)], 1);
        g_sx[pos] = p;
        g_sidx[pos] = i;
    }
}

// ---------------- bf16 helpers ----------------
__device__ __forceinline__ u16 f2bf(float v) {
    u16 r;
    asm("cvt.rn.bf16.f32 %0, %1;" : "=h"(r) : "f"(v));
    return r;
}
__device__ __forceinline__ float bf2f(u16 b) {
    float f;
    u32 w = ((u32)b) << 16;
    asm("mov.b32 %0, %1;" : "=f"(f) : "r"(w));
    return f;
}
// pack (lo, hi) floats -> bf16x2 word (lo in bits[0:16))
__device__ __forceinline__ u32 pack_bf(float lo, float hi) {
    u32 r;
    asm("cvt.rn.bf16x2.f32 %0, %1, %2;" : "=r"(r) : "f"(hi), "f"(lo));
    return r;
}

// ---------------- HMMA m16n8k16 bf16 (works on plain sm_103 target) --------
#define MMA(c, a0, a1, a2, a3, b0, b1)                                         \
    asm volatile(                                                              \
        "mma.sync.aligned.m16n8k16.row.col.f32.bf16.bf16.f32 "                 \
        "{%0,%1,%2,%3}, {%4,%5,%6,%7}, {%8,%9}, {%0,%1,%2,%3};"                \
        : "+f"((c)[0]), "+f"((c)[1]), "+f"((c)[2]), "+f"((c)[3])               \
        : "r"(a0), "r"(a1), "r"(a2), "r"(a3), "r"(b0), "r"(b1))

// ---------------- SMEM layout (bytes) ----------------
#define OFF_W1F 0         // fp32 w1 rows 0,1 (x,y): [2][64] = 512 B
#define OFF_W1 512        // W1' bf16 [n=64][stride 144 B] (36 words, ==4 mod 32)
#define OFF_W2 9728       // W2' bf16 [n=64][stride 400 B] (100 words, ==4 mod 32)
#define OFF_W3 35328      // fp32 [64][3] = 768 B
#define OFF_STAGE 36096   // per-warp: 32 rows x 73 words x 4 B = 9344 B; x8 warps
#define STG_STRIDE 73     // words per row (odd -> conflict-free writes)
#define SMEM_TOT (36096 + 8 * 9344)  // 110848

struct G4 { float2 f00, f10, f01, f11; float wx, wy; };

__device__ __forceinline__ void corner_idx(float2 p, int res, bool hashed,
                                           unsigned& i00, unsigned& i10,
                                           unsigned& i01, unsigned& i11,
                                           float& wx, float& wy) {
    float fx = p.x * (float)res, fy = p.y * (float)res;
    float x0 = floorf(fx), y0 = floorf(fy);
    wx = fx - x0; wy = fy - y0;
    unsigned xi = (unsigned)x0, yi = (unsigned)y0;
    if (hashed) {
        unsigned t0 = yi * PRIME_Y, t1 = (yi + 1u) * PRIME_Y;
        i00 = (xi ^ t0) & HMASK; i10 = ((xi + 1u) ^ t0) & HMASK;
        i01 = (xi ^ t1) & HMASK; i11 = ((xi + 1u) ^ t1) & HMASK;
    } else {
        unsigned s = (unsigned)res + 1u;
        unsigned b = xi + yi * s;
        i00 = b; i10 = b + 1u; i01 = b + s; i11 = b + s + 1u;
    }
}
__device__ __forceinline__ float2 bilerp(const G4& g) {
    float u = 1.f - g.wx, v = 1.f - g.wy;
    float w00 = u * v, w10 = g.wx * v, w01 = u * g.wy, w11 = g.wx * g.wy;
    return make_float2(
        g.f00.x * w00 + g.f10.x * w10 + g.f01.x * w01 + g.f11.x * w11,
        g.f00.y * w00 + g.f10.y * w10 + g.f01.y * w01 + g.f11.y * w11);
}

__global__ void __launch_bounds__(256, 2)
hashmlp_hmma_kernel(const float* __restrict__ tables,
                    const float* __restrict__ w1,
                    const float* __restrict__ w2,
                    const float* __restrict__ w3,
                    float* __restrict__ out, int n) {
    extern __shared__ unsigned char sraw[];
    const int tid = threadIdx.x;
    const int wid = tid >> 5;
    const int lane = tid & 31;
    const int lq = lane >> 2;   // 0..7 (row-in-half / n-in-tile)
    const int lr = lane & 3;    // 0..3 (col quad)

    float* w1f = (float*)(sraw + OFF_W1F);
    float* w3s = (float*)(sraw + OFF_W3);

    // ---- one-time weight staging ----
    for (int t = tid; t < 128; t += 256) w1f[t] = w1[t];  // rows 0,1 (x,y) fp32
    for (int idx = tid; idx < 32 * 64; idx += 256) {      // W1' features
        int f = idx >> 6, nn = idx & 63;
        *(u16*)(sraw + OFF_W1 + nn * 144 + 2 * f) = f2bf(w1[(2 + f) * 64 + nn]);
    }
    for (int idx = tid; idx < 64 * 64; idx += 256) {      // W2' 3-block
        int f = idx >> 6, nn = idx & 63;
        float v = w2[f * 64 + nn];
        u16 hb = f2bf(v);
        u16 lb = f2bf(v - bf2f(hb));
        unsigned char* base = sraw + OFF_W2 + nn * 400;
        *(u16*)(base + 2 * f) = hb;            // block 0: bh   (pairs A-hi)
        *(u16*)(base + 2 * (64 + f)) = hb;     // block 1: bh   (pairs A-lo)
        *(u16*)(base + 2 * (128 + f)) = lb;    // block 2: bl   (pairs A-hi)
    }
    for (int t = tid; t < 192; t += 256) w3s[t] = w3[t];
    __syncthreads();

    u32* stg = (u32*)(sraw + OFF_STAGE) + wid * (32 * STG_STRIDE);
    const u32* w1b = (const u32*)(sraw + OFF_W1);
    const u32* w2b = (const u32*)(sraw + OFF_W2);

    const int wbase = blockIdx.x * 256 + wid * 32;
    const int i = wbase + lane;
    const bool valid = i < n;
    const float2 p = valid ? g_sx[i] : make_float2(0.25f, 0.25f);
    const int oi = valid ? g_sidx[i] : 0;

    // ---- encode: 32 hash features (all levels via global; L1/L2-resident) ----
    float enc[32];
    G4 g;
    {
        unsigned a, b, c, d;
        corner_idx(p, RES_A[0], false, a, b, c, d, g.wx, g.wy);
        const float2* tb = (const float2*)tables;
        g.f00 = tb[a]; g.f10 = tb[b]; g.f01 = tb[c]; g.f11 = tb[d];
    }
#pragma unroll
    for (int l = 0; l < 16; l++) {
        G4 cur = g;
        if (l < 15) {
            unsigned a, b, c, d;
            corner_idx(p, RES_A[l + 1], (l + 1) >= 12, a, b, c, d, g.wx, g.wy);
            const float2* tb = (const float2*)tables + (size_t)(l + 1) * TABLE_SIZE;
            g.f00 = tb[a]; g.f10 = tb[b]; g.f01 = tb[c]; g.f11 = tb[d];
        }
        float2 f = bilerp(cur);
        enc[2 * l] = f.x; enc[2 * l + 1] = f.y;
    }

    // ---- stage L1 A: 16 bf16x2 words (feature cols 0..31) ----
#pragma unroll
    for (int j = 0; j < 16; j++)
        stg[lane * STG_STRIDE + j] = pack_bf(enc[2 * j], enc[2 * j + 1]);
    __syncwarp();

    // ---- C init: exact fp32 x,y contribution ----
    float C[8][2][4];
    const float xr0 = __shfl_sync(0xffffffffu, p.x, lq);
    const float yr0 = __shfl_sync(0xffffffffu, p.y, lq);
    const float xr8 = __shfl_sync(0xffffffffu, p.x, lq + 8);
    const float yr8 = __shfl_sync(0xffffffffu, p.y, lq + 8);
    const float xr16 = __shfl_sync(0xffffffffu, p.x, lq + 16);
    const float yr16 = __shfl_sync(0xffffffffu, p.y, lq + 16);
    const float xr24 = __shfl_sync(0xffffffffu, p.x, lq + 24);
    const float yr24 = __shfl_sync(0xffffffffu, p.y, lq + 24);
#pragma unroll
    for (int nt = 0; nt < 8; nt++) {
        int col = nt * 8 + lr * 2;
        float wx0 = w1f[col], wx1 = w1f[col + 1];
        float wy0 = w1f[64 + col], wy1 = w1f[64 + col + 1];
        C[nt][0][0] = xr0 * wx0 + yr0 * wy0;
        C[nt][0][1] = xr0 * wx1 + yr0 * wy1;
        C[nt][0][2] = xr8 * wx0 + yr8 * wy0;
        C[nt][0][3] = xr8 * wx1 + yr8 * wy1;
        C[nt][1][0] = xr16 * wx0 + yr16 * wy0;
        C[nt][1][1] = xr16 * wx1 + yr16 * wy1;
        C[nt][1][2] = xr24 * wx0 + yr24 * wy0;
        C[nt][1][3] = xr24 * wx1 + yr24 * wy1;
    }

    // ---- Layer 1 MMAs: 2 k-chunks x 2 m-tiles x 8 n-tiles ----
#pragma unroll
    for (int ch = 0; ch < 2; ch++) {
        int cw = ch * 8 + lr;
        u32 a0[2], a1[2], a2[2], a3[2];
#pragma unroll
        for (int m = 0; m < 2; m++) {
            int r = m * 16 + lq;
            a0[m] = stg[r * STG_STRIDE + cw];
            a1[m] = stg[(r + 8) * STG_STRIDE + cw];
            a2[m] = stg[r * STG_STRIDE + cw + 4];
            a3[m] = stg[(r + 8) * STG_STRIDE + cw + 4];
        }
#pragma unroll
        for (int nt = 0; nt < 8; nt++) {
            int nrow = nt * 8 + lq;
            u32 b0 = w1b[nrow * 36 + ch * 8 + lr];
            u32 b1 = w1b[nrow * 36 + ch * 8 + lr + 4];
            MMA(C[nt][0], a0[0], a1[0], a2[0], a3[0], b0, b1);
            MMA(C[nt][1], a0[1], a1[1], a2[1], a3[1], b0, b1);
        }
    }
    __syncwarp();

    // ---- ReLU + 2-block split staging (hi: words 0..31, lo: words 32..63) ----
#pragma unroll
    for (int nt = 0; nt < 8; nt++) {
#pragma unroll
        for (int m = 0; m < 2; m++) {
            int r = m * 16 + lq;
            float h0 = fmaxf(C[nt][m][0], 0.f), h1 = fmaxf(C[nt][m][1], 0.f);
            float h2 = fmaxf(C[nt][m][2], 0.f), h3 = fmaxf(C[nt][m][3], 0.f);
            int cwd = nt * 4 + lr;
            stg[r * STG_STRIDE + cwd] = pack_bf(h0, h1);
            stg[(r + 8) * STG_STRIDE + cwd] = pack_bf(h2, h3);
            float l0 = h0 - bf2f(f2bf(h0)), l1 = h1 - bf2f(f2bf(h1));
            float l2 = h2 - bf2f(f2bf(h2)), l3 = h3 - bf2f(f2bf(h3));
            stg[r * STG_STRIDE + 32 + cwd] = pack_bf(l0, l1);
            stg[(r + 8) * STG_STRIDE + 32 + cwd] = pack_bf(l2, l3);
        }
    }
    __syncwarp();

    // ---- zero C, Layer 2 MMAs: 12 chunks (A reuse for 8..11) ----
#pragma unroll
    for (int nt = 0; nt < 8; nt++)
#pragma unroll
        for (int m = 0; m < 2; m++)
#pragma unroll
            for (int k = 0; k < 4; k++) C[nt][m][k] = 0.f;

#pragma unroll
    for (int ch = 0; ch < 12; ch++) {
        int aw = ((ch < 8) ? ch : (ch - 8)) * 8 + lr;
        u32 a0[2], a1[2], a2[2], a3[2];
#pragma unroll
        for (int m = 0; m < 2; m++) {
            int r = m * 16 + lq;
            a0[m] = stg[r * STG_STRIDE + aw];
            a1[m] = stg[(r + 8) * STG_STRIDE + aw];
            a2[m] = stg[r * STG_STRIDE + aw + 4];
            a3[m] = stg[(r + 8) * STG_STRIDE + aw + 4];
        }
#pragma unroll
        for (int nt = 0; nt < 8; nt++) {
            int nrow = nt * 8 + lq;
            u32 b0 = w2b[nrow * 100 + ch * 8 + lr];
            u32 b1 = w2b[nrow * 100 + ch * 8 + lr + 4];
            MMA(C[nt][0], a0[0], a1[0], a2[0], a3[0], b0, b1);
            MMA(C[nt][1], a0[1], a1[1], a2[1], a3[1], b0, b1);
        }
    }

    // ---- ReLU + layer 3 partials (fp32) ----
    float po[4][3];
#pragma unroll
    for (int r = 0; r < 4; r++)
#pragma unroll
        for (int j = 0; j < 3; j++) po[r][j] = 0.f;
#pragma unroll
    for (int nt = 0; nt < 8; nt++) {
        int col = nt * 8 + lr * 2;
        float wa0 = w3s[col * 3], wa1 = w3s[col * 3 + 1], wa2 = w3s[col * 3 + 2];
        float wb0 = w3s[(col + 1) * 3], wb1 = w3s[(col + 1) * 3 + 1],
              wb2 = w3s[(col + 1) * 3 + 2];
#pragma unroll
        for (int m = 0; m < 2; m++) {
            float h0 = fmaxf(C[nt][m][0], 0.f), h1 = fmaxf(C[nt][m][1], 0.f);
            float h2 = fmaxf(C[nt][m][2], 0.f), h3 = fmaxf(C[nt][m][3], 0.f);
            po[2 * m][0] += h0 * wa0 + h1 * wb0;
            po[2 * m][1] += h0 * wa1 + h1 * wb1;
            po[2 * m][2] += h0 * wa2 + h1 * wb2;
            po[2 * m + 1][0] += h2 * wa0 + h3 * wb0;
            po[2 * m + 1][1] += h2 * wa1 + h3 * wb1;
            po[2 * m + 1][2] += h2 * wa2 + h3 * wb2;
        }
    }
    // quad reduction (lanes lr=0..3 hold disjoint col subsets)
#pragma unroll
    for (int r = 0; r < 4; r++)
#pragma unroll
        for (int j = 0; j < 3; j++) {
            po[r][j] += __shfl_xor_sync(0xffffffffu, po[r][j], 1);
            po[r][j] += __shfl_xor_sync(0xffffffffu, po[r][j], 2);
        }
    // gather original indices for the 4 rows this quad owns
    int rowsg[4] = {lq, lq + 8, lq + 16, lq + 24};
    int oir[4];
#pragma unroll
    for (int r = 0; r < 4; r++)
        oir[r] = __shfl_sync(0xffffffffu, oi, rowsg[r]);
    if (lr == 0) {
#pragma unroll
        for (int r = 0; r < 4; r++) {
            if (wbase + rowsg[r] < n) {
                size_t off = (size_t)oir[r] * 3;
                out[off] = po[r][0]; out[off + 1] = po[r][1]; out[off + 2] = po[r][2];
            }
        }
    }
}

extern "C" void kernel_launch(void* const* d_in, const int* in_sizes, int n_in,
                              void* d_out, int out_size) {
    const float* x      = (const float*)d_in[0];
    const float* tables = (const float*)d_in[1];
    const float* w1     = (const float*)d_in[2];
    const float* w2     = (const float*)d_in[3];
    const float* w3     = (const float*)d_in[4];
    float* out = (float*)d_out;

    const int n = in_sizes[0] / 2;
    const float2* x2 = (const float2*)x;

    zero_hist_k<<<NBINS / 256, 256>>>();
    hist_k<<<(n + 255) / 256, 256>>>(x2, n);
    scan_k<<<1, 1024>>>();
    scatter_k<<<(n + 255) / 256, 256>>>(x2, n);

    cudaFuncSetAttribute(hashmlp_hmma_kernel,
                         cudaFuncAttributeMaxDynamicSharedMemorySize, SMEM_TOT);
    hashmlp_hmma_kernel<<<(n + 255) / 256, 256, SMEM_TOT>>>(tables, w1, w2, w3,
                                                            out, n);
}

// round 11
// speedup vs baseline: 2.5384x; 1.0552x over previous
#include <cuda_runtime.h>
#include <cuda_bf16.h>
#include <cstdint>

typedef unsigned long long u64;
typedef unsigned int u32;
typedef unsigned short u16;

#define TABLE_SIZE 524288
#define HMASK 524287u
#define PRIME_Y 2654435761u
#define NPTS_MAX (1 << 21)
#define NBINS 16384

__device__ constexpr int RES_A[16] = {16, 22, 30, 42, 58, 80, 111, 153, 212,
                                      294, 406, 561, 775, 1072, 1481, 2047};

// ---------------- sort scratch ----------------
__device__ int g_hist[NBINS];
__device__ int g_off[NBINS];
__device__ int g_sidx[NPTS_MAX];

// ---------------- Morton sort kernels ----------------
__device__ __forceinline__ unsigned spread8(unsigned v) {
    v &= 0xFFu;
    v = (v | (v << 4)) & 0x0F0Fu;
    v = (v | (v << 2)) & 0x3333u;
    v = (v | (v << 1)) & 0x5555u;
    return v;
}
__device__ __forceinline__ int morton_key(float2 p) {
    unsigned cx = (unsigned)(p.x * 128.0f);
    unsigned cy = (unsigned)(p.y * 128.0f);
    cx = cx > 127u ? 127u : cx;
    cy = cy > 127u ? 127u : cy;
    return (int)(spread8(cx) | (spread8(cy) << 1));
}
__global__ void zero_hist_k() {
    int i = blockIdx.x * blockDim.x + threadIdx.x;
    if (i < NBINS) g_hist[i] = 0;
}
__global__ void hist_k(const float2* __restrict__ x, int n) {
    int i = blockIdx.x * blockDim.x + threadIdx.x;
    if (i < n) atomicAdd(&g_hist[morton_key(x[i])], 1);
}
__global__ void scan_k() {
    __shared__ int tot[1024];
    const int t = threadIdx.x;
    const int base = t * 16;
    int loc[16];
    int s = 0;
#pragma unroll
    for (int k = 0; k < 16; k++) { loc[k] = g_hist[base + k]; s += loc[k]; }
    tot[t] = s;
    __syncthreads();
    for (int off = 1; off < 1024; off <<= 1) {
        int v = (t >= off) ? tot[t - off] : 0;
        __syncthreads();
        tot[t] += v;
        __syncthreads();
    }
    int run = tot[t] - s;
#pragma unroll
    for (int k = 0; k < 16; k++) { g_off[base + k] = run; run += loc[k]; }
}
__global__ void scatter_k(const float2* __restrict__ x, int n) {
    int i = blockIdx.x * blockDim.x + threadIdx.x;
    if (i < n) {
        int pos = atomicAdd(&g_off[morton_key(x[i])], 1);
        g_sidx[pos] = i;
    }
}

// ---------------- bf16 helpers ----------------
__device__ __forceinline__ u16 f2bf(float v) {
    u16 r;
    asm("cvt.rn.bf16.f32 %0, %1;" : "=h"(r) : "f"(v));
    return r;
}
__device__ __forceinline__ float bf2f(u16 b) {
    float f;
    u32 w = ((u32)b) << 16;
    asm("mov.b32 %0, %1;" : "=f"(f) : "r"(w));
    return f;
}
__device__ __forceinline__ u32 pack_bf(float lo, float hi) {
    u32 r;
    asm("cvt.rn.bf16x2.f32 %0, %1, %2;" : "=r"(r) : "f"(hi), "f"(lo));
    return r;
}

// ---------------- HMMA m16n8k16 bf16 ----------------
#define MMA(c, a0, a1, a2, a3, b0, b1)                                         \
    asm volatile(                                                              \
        "mma.sync.aligned.m16n8k16.row.col.f32.bf16.bf16.f32 "                 \
        "{%0,%1,%2,%3}, {%4,%5,%6,%7}, {%8,%9}, {%0,%1,%2,%3};"                \
        : "+f"((c)[0]), "+f"((c)[1]), "+f"((c)[2]), "+f"((c)[3])               \
        : "r"(a0), "r"(a1), "r"(a2), "r"(a3), "r"(b0), "r"(b1))

// ldmatrix x4 transposed (B fragments from row-major [k][n] storage)
__device__ __forceinline__ void ldsm4t(u32& r0, u32& r1, u32& r2, u32& r3,
                                       u32 addr) {
    asm volatile(
        "ldmatrix.sync.aligned.m8n8.x4.trans.shared.b16 {%0,%1,%2,%3}, [%4];"
        : "=r"(r0), "=r"(r1), "=r"(r2), "=r"(r3) : "r"(addr));
}
__device__ __forceinline__ u32 smem_u32(const void* p) {
    u32 a;
    asm("{ .reg .u64 t; cvta.to.shared.u64 t, %1; cvt.u32.u64 %0, t; }"
        : "=r"(a) : "l"(p));
    return a;
}

// ---------------- SMEM layout (bytes) ----------------
// W1'/W2' stored row-major [k][n=64 bf16], row stride 144 B (conflict-free LDSM)
#define OFF_W1F 0          // fp32 w1 rows 0,1 (x,y): 512 B
#define OFF_W1 512         // bf16 [32 k][144 B] = 4608 B
#define OFF_W2 5120        // bf16 [192 k'][144 B] = 27648 B
#define OFF_W3 32768       // fp32 [64][3] = 768 B
#define OFF_STAGE 33536    // per-warp: 32 rows x 73 words x 4 B = 9344 B; x8
#define STG_STRIDE 73
#define SMEM_TOT (33536 + 8 * 9344)  // 108288

struct G4 { float2 f00, f10, f01, f11; float wx, wy; };

__device__ __forceinline__ void corner_idx(float2 p, int res, bool hashed,
                                           unsigned& i00, unsigned& i10,
                                           unsigned& i01, unsigned& i11,
                                           float& wx, float& wy) {
    float fx = p.x * (float)res, fy = p.y * (float)res;
    float x0 = floorf(fx), y0 = floorf(fy);
    wx = fx - x0; wy = fy - y0;
    unsigned xi = (unsigned)x0, yi = (unsigned)y0;
    if (hashed) {
        unsigned t0 = yi * PRIME_Y, t1 = (yi + 1u) * PRIME_Y;
        i00 = (xi ^ t0) & HMASK; i10 = ((xi + 1u) ^ t0) & HMASK;
        i01 = (xi ^ t1) & HMASK; i11 = ((xi + 1u) ^ t1) & HMASK;
    } else {
        unsigned s = (unsigned)res + 1u;
        unsigned b = xi + yi * s;
        i00 = b; i10 = b + 1u; i01 = b + s; i11 = b + s + 1u;
    }
}
__device__ __forceinline__ float2 bilerp(const G4& g) {
    float u = 1.f - g.wx, v = 1.f - g.wy;
    float w00 = u * v, w10 = g.wx * v, w01 = u * g.wy, w11 = g.wx * g.wy;
    return make_float2(
        g.f00.x * w00 + g.f10.x * w10 + g.f01.x * w01 + g.f11.x * w11,
        g.f00.y * w00 + g.f10.y * w10 + g.f01.y * w01 + g.f11.y * w11);
}

__global__ void __launch_bounds__(256, 2)
hashmlp_hmma_kernel(const float2* __restrict__ xin,
                    const float* __restrict__ tables,
                    const float* __restrict__ w1,
                    const float* __restrict__ w2,
                    const float* __restrict__ w3,
                    float* __restrict__ out, int n) {
    extern __shared__ unsigned char sraw[];
    const int tid = threadIdx.x;
    const int wid = tid >> 5;
    const int lane = tid & 31;
    const int lq = lane >> 2;   // 0..7
    const int lr = lane & 3;    // 0..3

    float* w1f = (float*)(sraw + OFF_W1F);
    float* w3s = (float*)(sraw + OFF_W3);

    // ---- one-time weight staging ----
    for (int t = tid; t < 128; t += 256) w1f[t] = w1[t];  // rows 0,1 fp32
    for (int idx = tid; idx < 32 * 64; idx += 256) {      // W1' [k=f][n]
        int f = idx >> 6, nn = idx & 63;
        *(u16*)(sraw + OFF_W1 + f * 144 + nn * 2) = f2bf(w1[(2 + f) * 64 + nn]);
    }
    for (int idx = tid; idx < 64 * 64; idx += 256) {      // W2' 3-block [k'][n]
        int f = idx >> 6, nn = idx & 63;
        float v = w2[f * 64 + nn];
        u16 hb = f2bf(v);
        u16 lb = f2bf(v - bf2f(hb));
        *(u16*)(sraw + OFF_W2 + f * 144 + nn * 2) = hb;          // k' = f
        *(u16*)(sraw + OFF_W2 + (64 + f) * 144 + nn * 2) = hb;   // k' = 64+f
        *(u16*)(sraw + OFF_W2 + (128 + f) * 144 + nn * 2) = lb;  // k' = 128+f
    }
    for (int t = tid; t < 192; t += 256) w3s[t] = w3[t];
    __syncthreads();

    u32* stg = (u32*)(sraw + OFF_STAGE) + wid * (32 * STG_STRIDE);
    const u32 sbase = smem_u32(sraw);
    // per-lane ldmatrix offset: row within sub-matrix, k-sub, n-sub
    const u32 lm_off = (u32)((lane & 7) * 144 + ((lane >> 3) & 1) * (8 * 144) +
                             (lane >> 4) * 16);
    const u32 w1base = sbase + OFF_W1 + lm_off;
    const u32 w2base = sbase + OFF_W2 + lm_off;

    const int wbase = blockIdx.x * 256 + wid * 32;
    const int i = wbase + lane;
    const bool valid = i < n;
    const int oi = valid ? g_sidx[i] : 0;
    const float2 p = valid ? xin[oi] : make_float2(0.25f, 0.25f);

    // ---- encode: 32 hash features ----
    float enc[32];
    G4 g;
    {
        unsigned a, b, c, d;
        corner_idx(p, RES_A[0], false, a, b, c, d, g.wx, g.wy);
        const float2* tb = (const float2*)tables;
        g.f00 = tb[a]; g.f10 = tb[b]; g.f01 = tb[c]; g.f11 = tb[d];
    }
#pragma unroll
    for (int l = 0; l < 16; l++) {
        G4 cur = g;
        if (l < 15) {
            unsigned a, b, c, d;
            corner_idx(p, RES_A[l + 1], (l + 1) >= 12, a, b, c, d, g.wx, g.wy);
            const float2* tb = (const float2*)tables + (size_t)(l + 1) * TABLE_SIZE;
            g.f00 = tb[a]; g.f10 = tb[b]; g.f01 = tb[c]; g.f11 = tb[d];
        }
        float2 f = bilerp(cur);
        enc[2 * l] = f.x; enc[2 * l + 1] = f.y;
    }

    // ---- stage L1 A (16 bf16x2 words/point) ----
#pragma unroll
    for (int j = 0; j < 16; j++)
        stg[lane * STG_STRIDE + j] = pack_bf(enc[2 * j], enc[2 * j + 1]);
    __syncwarp();

    // ---- C init: exact fp32 x,y contribution ----
    float C[8][2][4];
    const float xr0 = __shfl_sync(0xffffffffu, p.x, lq);
    const float yr0 = __shfl_sync(0xffffffffu, p.y, lq);
    const float xr8 = __shfl_sync(0xffffffffu, p.x, lq + 8);
    const float yr8 = __shfl_sync(0xffffffffu, p.y, lq + 8);
    const float xr16 = __shfl_sync(0xffffffffu, p.x, lq + 16);
    const float yr16 = __shfl_sync(0xffffffffu, p.y, lq + 16);
    const float xr24 = __shfl_sync(0xffffffffu, p.x, lq + 24);
    const float yr24 = __shfl_sync(0xffffffffu, p.y, lq + 24);
#pragma unroll
    for (int nt = 0; nt < 8; nt++) {
        int col = nt * 8 + lr * 2;
        float wx0 = w1f[col], wx1 = w1f[col + 1];
        float wy0 = w1f[64 + col], wy1 = w1f[64 + col + 1];
        C[nt][0][0] = xr0 * wx0 + yr0 * wy0;
        C[nt][0][1] = xr0 * wx1 + yr0 * wy1;
        C[nt][0][2] = xr8 * wx0 + yr8 * wy0;
        C[nt][0][3] = xr8 * wx1 + yr8 * wy1;
        C[nt][1][0] = xr16 * wx0 + yr16 * wy0;
        C[nt][1][1] = xr16 * wx1 + yr16 * wy1;
        C[nt][1][2] = xr24 * wx0 + yr24 * wy0;
        C[nt][1][3] = xr24 * wx1 + yr24 * wy1;
    }

    // ---- Layer 1 MMAs: 2 k-chunks, B via ldmatrix ----
#pragma unroll
    for (int ch = 0; ch < 2; ch++) {
        int cw = ch * 8 + lr;
        u32 a0[2], a1[2], a2[2], a3[2];
#pragma unroll
        for (int m = 0; m < 2; m++) {
            int r = m * 16 + lq;
            a0[m] = stg[r * STG_STRIDE + cw];
            a1[m] = stg[(r + 8) * STG_STRIDE + cw];
            a2[m] = stg[r * STG_STRIDE + cw + 4];
            a3[m] = stg[(r + 8) * STG_STRIDE + cw + 4];
        }
#pragma unroll
        for (int np = 0; np < 4; np++) {
            u32 b0, b1, b2, b3;
            ldsm4t(b0, b1, b2, b3, w1base + ch * (16 * 144) + np * 32);
            MMA(C[2 * np][0], a0[0], a1[0], a2[0], a3[0], b0, b1);
            MMA(C[2 * np][1], a0[1], a1[1], a2[1], a3[1], b0, b1);
            MMA(C[2 * np + 1][0], a0[0], a1[0], a2[0], a3[0], b2, b3);
            MMA(C[2 * np + 1][1], a0[1], a1[1], a2[1], a3[1], b2, b3);
        }
    }
    __syncwarp();

    // ---- ReLU + 2-block split staging (hi: words 0..31, lo: 32..63) ----
#pragma unroll
    for (int nt = 0; nt < 8; nt++) {
#pragma unroll
        for (int m = 0; m < 2; m++) {
            int r = m * 16 + lq;
            float h0 = fmaxf(C[nt][m][0], 0.f), h1 = fmaxf(C[nt][m][1], 0.f);
            float h2 = fmaxf(C[nt][m][2], 0.f), h3 = fmaxf(C[nt][m][3], 0.f);
            int cwd = nt * 4 + lr;
            stg[r * STG_STRIDE + cwd] = pack_bf(h0, h1);
            stg[(r + 8) * STG_STRIDE + cwd] = pack_bf(h2, h3);
            float l0 = h0 - bf2f(f2bf(h0)), l1 = h1 - bf2f(f2bf(h1));
            float l2 = h2 - bf2f(f2bf(h2)), l3 = h3 - bf2f(f2bf(h3));
            stg[r * STG_STRIDE + 32 + cwd] = pack_bf(l0, l1);
            stg[(r + 8) * STG_STRIDE + 32 + cwd] = pack_bf(l2, l3);
        }
    }
    __syncwarp();

    // ---- zero C, Layer 2: 12 chunks (A hi/lo/hi; B bh/bh/bl rows) ----
#pragma unroll
    for (int nt = 0; nt < 8; nt++)
#pragma unroll
        for (int m = 0; m < 2; m++)
#pragma unroll
            for (int k = 0; k < 4; k++) C[nt][m][k] = 0.f;

#pragma unroll
    for (int ch = 0; ch < 12; ch++) {
        int aw = ((ch < 8) ? ch : (ch - 8)) * 8 + lr;
        u32 a0[2], a1[2], a2[2], a3[2];
#pragma unroll
        for (int m = 0; m < 2; m++) {
            int r = m * 16 + lq;
            a0[m] = stg[r * STG_STRIDE + aw];
            a1[m] = stg[(r + 8) * STG_STRIDE + aw];
            a2[m] = stg[r * STG_STRIDE + aw + 4];
            a3[m] = stg[(r + 8) * STG_STRIDE + aw + 4];
        }
#pragma unroll
        for (int np = 0; np < 4; np++) {
            u32 b0, b1, b2, b3;
            ldsm4t(b0, b1, b2, b3, w2base + ch * (16 * 144) + np * 32);
            MMA(C[2 * np][0], a0[0], a1[0], a2[0], a3[0], b0, b1);
            MMA(C[2 * np][1], a0[1], a1[1], a2[1], a3[1], b0, b1);
            MMA(C[2 * np + 1][0], a0[0], a1[0], a2[0], a3[0], b2, b3);
            MMA(C[2 * np + 1][1], a0[1], a1[1], a2[1], a3[1], b2, b3);
        }
    }

    // ---- ReLU + layer 3 partials (fp32) ----
    float po[4][3];
#pragma unroll
    for (int r = 0; r < 4; r++)
#pragma unroll
        for (int j = 0; j < 3; j++) po[r][j] = 0.f;
#pragma unroll
    for (int nt = 0; nt < 8; nt++) {
        int col = nt * 8 + lr * 2;
        float wa0 = w3s[col * 3], wa1 = w3s[col * 3 + 1], wa2 = w3s[col * 3 + 2];
        float wb0 = w3s[(col + 1) * 3], wb1 = w3s[(col + 1) * 3 + 1],
              wb2 = w3s[(col + 1) * 3 + 2];
#pragma unroll
        for (int m = 0; m < 2; m++) {
            float h0 = fmaxf(C[nt][m][0], 0.f), h1 = fmaxf(C[nt][m][1], 0.f);
            float h2 = fmaxf(C[nt][m][2], 0.f), h3 = fmaxf(C[nt][m][3], 0.f);
            po[2 * m][0] += h0 * wa0 + h1 * wb0;
            po[2 * m][1] += h0 * wa1 + h1 * wb1;
            po[2 * m][2] += h0 * wa2 + h1 * wb2;
            po[2 * m + 1][0] += h2 * wa0 + h3 * wb0;
            po[2 * m + 1][1] += h2 * wa1 + h3 * wb1;
            po[2 * m + 1][2] += h2 * wa2 + h3 * wb2;
        }
    }
#pragma unroll
    for (int r = 0; r < 4; r++)
#pragma unroll
        for (int j = 0; j < 3; j++) {
            po[r][j] += __shfl_xor_sync(0xffffffffu, po[r][j], 1);
            po[r][j] += __shfl_xor_sync(0xffffffffu, po[r][j], 2);
        }
    int rowsg[4] = {lq, lq + 8, lq + 16, lq + 24};
    int oir[4];
#pragma unroll
    for (int r = 0; r < 4; r++)
        oir[r] = __shfl_sync(0xffffffffu, oi, rowsg[r]);
    if (lr == 0) {
#pragma unroll
        for (int r = 0; r < 4; r++) {
            if (wbase + rowsg[r] < n) {
                size_t off = (size_t)oir[r] * 3;
                out[off] = po[r][0]; out[off + 1] = po[r][1]; out[off + 2] = po[r][2];
            }
        }
    }
}

extern "C" void kernel_launch(void* const* d_in, const int* in_sizes, int n_in,
                              void* d_out, int out_size) {
    const float* x      = (const float*)d_in[0];
    const float* tables = (const float*)d_in[1];
    const float* w1     = (const float*)d_in[2];
    const float* w2     = (const float*)d_in[3];
    const float* w3     = (const float*)d_in[4];
    float* out = (float*)d_out;

    const int n = in_sizes[0] / 2;
    const float2* x2 = (const float2*)x;

    zero_hist_k<<<NBINS / 256, 256>>>();
    hist_k<<<(n + 255) / 256, 256>>>(x2, n);
    scan_k<<<1, 1024>>>();
    scatter_k<<<(n + 255) / 256, 256>>>(x2, n);

    cudaFuncSetAttribute(hashmlp_hmma_kernel,
                         cudaFuncAttributeMaxDynamicSharedMemorySize, SMEM_TOT);
    hashmlp_hmma_kernel<<<(n + 255) / 256, 256, SMEM_TOT>>>(x2, tables, w1, w2,
                                                            w3, out, n);
}

// round 12
// speedup vs baseline: 2.5900x; 1.0203x over previous
#include <cuda_runtime.h>
#include <cuda_bf16.h>
#include <cstdint>

typedef unsigned long long u64;
typedef unsigned int u32;
typedef unsigned short u16;

#define TABLE_SIZE 524288
#define HMASK 524287u
#define PRIME_Y 2654435761u
#define NPTS_MAX (1 << 21)
#define NBINS 16384

__device__ constexpr int RES_A[16] = {16, 22, 30, 42, 58, 80, 111, 153, 212,
                                      294, 406, 561, 775, 1072, 1481, 2047};

// ---------------- sort scratch ----------------
__device__ int g_hist[NBINS];
__device__ int g_off[NBINS];
__device__ int g_sidx[NPTS_MAX];

// ---------------- Morton sort kernels ----------------
__device__ __forceinline__ unsigned spread8(unsigned v) {
    v &= 0xFFu;
    v = (v | (v << 4)) & 0x0F0Fu;
    v = (v | (v << 2)) & 0x3333u;
    v = (v | (v << 1)) & 0x5555u;
    return v;
}
__device__ __forceinline__ int morton_key(float2 p) {
    unsigned cx = (unsigned)(p.x * 128.0f);
    unsigned cy = (unsigned)(p.y * 128.0f);
    cx = cx > 127u ? 127u : cx;
    cy = cy > 127u ? 127u : cy;
    return (int)(spread8(cx) | (spread8(cy) << 1));
}
__global__ void zero_hist_k() {
    int i = blockIdx.x * blockDim.x + threadIdx.x;
    if (i < NBINS) g_hist[i] = 0;
}
__global__ void hist_k(const float2* __restrict__ x, int n) {
    int i = blockIdx.x * blockDim.x + threadIdx.x;
    if (i < n) atomicAdd(&g_hist[morton_key(x[i])], 1);
}
__global__ void scan_k() {
    __shared__ int tot[1024];
    const int t = threadIdx.x;
    const int base = t * 16;
    int loc[16];
    int s = 0;
#pragma unroll
    for (int k = 0; k < 16; k++) { loc[k] = g_hist[base + k]; s += loc[k]; }
    tot[t] = s;
    __syncthreads();
    for (int off = 1; off < 1024; off <<= 1) {
        int v = (t >= off) ? tot[t - off] : 0;
        __syncthreads();
        tot[t] += v;
        __syncthreads();
    }
    int run = tot[t] - s;
#pragma unroll
    for (int k = 0; k < 16; k++) { g_off[base + k] = run; run += loc[k]; }
}
__global__ void scatter_k(const float2* __restrict__ x, int n) {
    int i = blockIdx.x * blockDim.x + threadIdx.x;
    if (i < n) {
        int pos = atomicAdd(&g_off[morton_key(x[i])], 1);
        g_sidx[pos] = i;
    }
}

// ---------------- bf16 helpers ----------------
__device__ __forceinline__ u16 f2bf(float v) {
    u16 r;
    asm("cvt.rn.bf16.f32 %0, %1;" : "=h"(r) : "f"(v));
    return r;
}
__device__ __forceinline__ float bf2f(u16 b) {
    float f;
    u32 w = ((u32)b) << 16;
    asm("mov.b32 %0, %1;" : "=f"(f) : "r"(w));
    return f;
}
__device__ __forceinline__ u32 pack_bf(float lo, float hi) {
    u32 r;
    asm("cvt.rn.bf16x2.f32 %0, %1, %2;" : "=r"(r) : "f"(hi), "f"(lo));
    return r;
}

// ---------------- HMMA m16n8k16 bf16 ----------------
#define MMA(c, a0, a1, a2, a3, b0, b1)                                         \
    asm volatile(                                                              \
        "mma.sync.aligned.m16n8k16.row.col.f32.bf16.bf16.f32 "                 \
        "{%0,%1,%2,%3}, {%4,%5,%6,%7}, {%8,%9}, {%0,%1,%2,%3};"                \
        : "+f"((c)[0]), "+f"((c)[1]), "+f"((c)[2]), "+f"((c)[3])               \
        : "r"(a0), "r"(a1), "r"(a2), "r"(a3), "r"(b0), "r"(b1))

// ldmatrix x4 transposed (B fragments from row-major [k][n] storage)
__device__ __forceinline__ void ldsm4t(u32& r0, u32& r1, u32& r2, u32& r3,
                                       u32 addr) {
    asm volatile(
        "ldmatrix.sync.aligned.m8n8.x4.trans.shared.b16 {%0,%1,%2,%3}, [%4];"
        : "=r"(r0), "=r"(r1), "=r"(r2), "=r"(r3) : "r"(addr));
}
__device__ __forceinline__ u32 smem_u32(const void* p) {
    u32 a;
    asm("{ .reg .u64 t; cvta.to.shared.u64 t, %1; cvt.u32.u64 %0, t; }"
        : "=r"(a) : "l"(p));
    return a;
}

// ---------------- SMEM layout (bytes) ----------------
#define OFF_W1F 0          // fp32 w1 rows 0,1 (x,y): 512 B
#define OFF_W1 512         // bf16 [32 k][144 B] = 4608 B
#define OFF_W2 5120        // bf16 [192 k'][144 B] = 27648 B
#define OFF_W3 32768       // fp32 [64][3] = 768 B
#define OFF_STAGE 33536    // per-warp: 32 rows x 73 words x 4 B = 9344 B; x8
#define STG_STRIDE 73
#define SMEM_TOT (33536 + 8 * 9344)  // 108288

__device__ __forceinline__ void corner_idx(float2 p, int res, bool hashed,
                                           unsigned& i00, unsigned& i10,
                                           unsigned& i01, unsigned& i11,
                                           float& wx, float& wy) {
    float fx = p.x * (float)res, fy = p.y * (float)res;
    float x0 = floorf(fx), y0 = floorf(fy);
    wx = fx - x0; wy = fy - y0;
    unsigned xi = (unsigned)x0, yi = (unsigned)y0;
    if (hashed) {
        unsigned t0 = yi * PRIME_Y, t1 = (yi + 1u) * PRIME_Y;
        i00 = (xi ^ t0) & HMASK; i10 = ((xi + 1u) ^ t0) & HMASK;
        i01 = (xi ^ t1) & HMASK; i11 = ((xi + 1u) ^ t1) & HMASK;
    } else {
        unsigned s = (unsigned)res + 1u;
        unsigned b = xi + yi * s;
        i00 = b; i10 = b + 1u; i01 = b + s; i11 = b + s + 1u;
    }
}

__global__ void __launch_bounds__(256, 2)
hashmlp_hmma_kernel(const float2* __restrict__ xin,
                    const float* __restrict__ tables,
                    const float* __restrict__ w1,
                    const float* __restrict__ w2,
                    const float* __restrict__ w3,
                    float* __restrict__ out, int n) {
    extern __shared__ unsigned char sraw[];
    const int tid = threadIdx.x;
    const int wid = tid >> 5;
    const int lane = tid & 31;
    const int lq = lane >> 2;   // 0..7
    const int lr = lane & 3;    // 0..3

    float* w1f = (float*)(sraw + OFF_W1F);
    float* w3s = (float*)(sraw + OFF_W3);

    // ---- one-time weight staging ----
    for (int t = tid; t < 128; t += 256) w1f[t] = w1[t];  // rows 0,1 fp32
    for (int idx = tid; idx < 32 * 64; idx += 256) {      // W1' [k=f][n]
        int f = idx >> 6, nn = idx & 63;
        *(u16*)(sraw + OFF_W1 + f * 144 + nn * 2) = f2bf(w1[(2 + f) * 64 + nn]);
    }
    for (int idx = tid; idx < 64 * 64; idx += 256) {      // W2' 3-block [k'][n]
        int f = idx >> 6, nn = idx & 63;
        float v = w2[f * 64 + nn];
        u16 hb = f2bf(v);
        u16 lb = f2bf(v - bf2f(hb));
        *(u16*)(sraw + OFF_W2 + f * 144 + nn * 2) = hb;          // k' = f
        *(u16*)(sraw + OFF_W2 + (64 + f) * 144 + nn * 2) = hb;   // k' = 64+f
        *(u16*)(sraw + OFF_W2 + (128 + f) * 144 + nn * 2) = lb;  // k' = 128+f
    }
    for (int t = tid; t < 192; t += 256) w3s[t] = w3[t];
    __syncthreads();

    u32* stg = (u32*)(sraw + OFF_STAGE) + wid * (32 * STG_STRIDE);
    const u32 sbase = smem_u32(sraw);
    const u32 lm_off = (u32)((lane & 7) * 144 + ((lane >> 3) & 1) * (8 * 144) +
                             (lane >> 4) * 16);
    const u32 w1base = sbase + OFF_W1 + lm_off;
    const u32 w2base = sbase + OFF_W2 + lm_off;

    const int wbase = blockIdx.x * 256 + wid * 32;
    const int i = wbase + lane;
    const bool valid = i < n;
    const int oi = valid ? g_sidx[i] : 0;
    const float2 p = valid ? xin[oi] : make_float2(0.25f, 0.25f);

    // ---- encode: 4 batches of 4 levels; batched loads (MLP=16/batch),
    //      features packed straight into the stage buffer ----
#pragma unroll
    for (int b = 0; b < 4; b++) {
        unsigned ida[4][4];
        float wxl[4], wyl[4];
#pragma unroll
        for (int q = 0; q < 4; q++) {
            int l = b * 4 + q;
            corner_idx(p, RES_A[l], l >= 12, ida[q][0], ida[q][1], ida[q][2],
                       ida[q][3], wxl[q], wyl[q]);
        }
        float2 cf[4][4];
#pragma unroll
        for (int q = 0; q < 4; q++) {
            const float2* tb =
                (const float2*)tables + (size_t)(b * 4 + q) * TABLE_SIZE;
            cf[q][0] = tb[ida[q][0]];
            cf[q][1] = tb[ida[q][1]];
            cf[q][2] = tb[ida[q][2]];
            cf[q][3] = tb[ida[q][3]];
        }
#pragma unroll
        for (int q = 0; q < 4; q++) {
            float u = 1.f - wxl[q], v = 1.f - wyl[q];
            float w00 = u * v, w10 = wxl[q] * v, w01 = u * wyl[q],
                  w11 = wxl[q] * wyl[q];
            float fx = cf[q][0].x * w00 + cf[q][1].x * w10 + cf[q][2].x * w01 +
                       cf[q][3].x * w11;
            float fy = cf[q][0].y * w00 + cf[q][1].y * w10 + cf[q][2].y * w01 +
                       cf[q][3].y * w11;
            stg[lane * STG_STRIDE + b * 4 + q] = pack_bf(fx, fy);
        }
    }
    __syncwarp();

    // ---- C init: exact fp32 x,y contribution ----
    float C[8][2][4];
    const float xr0 = __shfl_sync(0xffffffffu, p.x, lq);
    const float yr0 = __shfl_sync(0xffffffffu, p.y, lq);
    const float xr8 = __shfl_sync(0xffffffffu, p.x, lq + 8);
    const float yr8 = __shfl_sync(0xffffffffu, p.y, lq + 8);
    const float xr16 = __shfl_sync(0xffffffffu, p.x, lq + 16);
    const float yr16 = __shfl_sync(0xffffffffu, p.y, lq + 16);
    const float xr24 = __shfl_sync(0xffffffffu, p.x, lq + 24);
    const float yr24 = __shfl_sync(0xffffffffu, p.y, lq + 24);
#pragma unroll
    for (int nt = 0; nt < 8; nt++) {
        int col = nt * 8 + lr * 2;
        float wx0 = w1f[col], wx1 = w1f[col + 1];
        float wy0 = w1f[64 + col], wy1 = w1f[64 + col + 1];
        C[nt][0][0] = xr0 * wx0 + yr0 * wy0;
        C[nt][0][1] = xr0 * wx1 + yr0 * wy1;
        C[nt][0][2] = xr8 * wx0 + yr8 * wy0;
        C[nt][0][3] = xr8 * wx1 + yr8 * wy1;
        C[nt][1][0] = xr16 * wx0 + yr16 * wy0;
        C[nt][1][1] = xr16 * wx1 + yr16 * wy1;
        C[nt][1][2] = xr24 * wx0 + yr24 * wy0;
        C[nt][1][3] = xr24 * wx1 + yr24 * wy1;
    }

    // ---- Layer 1 MMAs: 2 k-chunks, B via ldmatrix ----
#pragma unroll
    for (int ch = 0; ch < 2; ch++) {
        int cw = ch * 8 + lr;
        u32 a0[2], a1[2], a2[2], a3[2];
#pragma unroll
        for (int m = 0; m < 2; m++) {
            int r = m * 16 + lq;
            a0[m] = stg[r * STG_STRIDE + cw];
            a1[m] = stg[(r + 8) * STG_STRIDE + cw];
            a2[m] = stg[r * STG_STRIDE + cw + 4];
            a3[m] = stg[(r + 8) * STG_STRIDE + cw + 4];
        }
#pragma unroll
        for (int np = 0; np < 4; np++) {
            u32 b0, b1, b2, b3;
            ldsm4t(b0, b1, b2, b3, w1base + ch * (16 * 144) + np * 32);
            MMA(C[2 * np][0], a0[0], a1[0], a2[0], a3[0], b0, b1);
            MMA(C[2 * np][1], a0[1], a1[1], a2[1], a3[1], b0, b1);
            MMA(C[2 * np + 1][0], a0[0], a1[0], a2[0], a3[0], b2, b3);
            MMA(C[2 * np + 1][1], a0[1], a1[1], a2[1], a3[1], b2, b3);
        }
    }
    __syncwarp();

    // ---- ReLU + 2-block split staging (hi: words 0..31, lo: 32..63) ----
#pragma unroll
    for (int nt = 0; nt < 8; nt++) {
#pragma unroll
        for (int m = 0; m < 2; m++) {
            int r = m * 16 + lq;
            float h0 = fmaxf(C[nt][m][0], 0.f), h1 = fmaxf(C[nt][m][1], 0.f);
            float h2 = fmaxf(C[nt][m][2], 0.f), h3 = fmaxf(C[nt][m][3], 0.f);
            int cwd = nt * 4 + lr;
            stg[r * STG_STRIDE + cwd] = pack_bf(h0, h1);
            stg[(r + 8) * STG_STRIDE + cwd] = pack_bf(h2, h3);
            float l0 = h0 - bf2f(f2bf(h0)), l1 = h1 - bf2f(f2bf(h1));
            float l2 = h2 - bf2f(f2bf(h2)), l3 = h3 - bf2f(f2bf(h3));
            stg[r * STG_STRIDE + 32 + cwd] = pack_bf(l0, l1);
            stg[(r + 8) * STG_STRIDE + 32 + cwd] = pack_bf(l2, l3);
        }
    }
    __syncwarp();

    // ---- zero C, Layer 2: 12 chunks (A hi/lo/hi; B bh/bh/bl rows) ----
#pragma unroll
    for (int nt = 0; nt < 8; nt++)
#pragma unroll
        for (int m = 0; m < 2; m++)
#pragma unroll
            for (int k = 0; k < 4; k++) C[nt][m][k] = 0.f;

#pragma unroll
    for (int ch = 0; ch < 12; ch++) {
        int aw = ((ch < 8) ? ch : (ch - 8)) * 8 + lr;
        u32 a0[2], a1[2], a2[2], a3[2];
#pragma unroll
        for (int m = 0; m < 2; m++) {
            int r = m * 16 + lq;
            a0[m] = stg[r * STG_STRIDE + aw];
            a1[m] = stg[(r + 8) * STG_STRIDE + aw];
            a2[m] = stg[r * STG_STRIDE + aw + 4];
            a3[m] = stg[(r + 8) * STG_STRIDE + aw + 4];
        }
#pragma unroll
        for (int np = 0; np < 4; np++) {
            u32 b0, b1, b2, b3;
            ldsm4t(b0, b1, b2, b3, w2base + ch * (16 * 144) + np * 32);
            MMA(C[2 * np][0], a0[0], a1[0], a2[0], a3[0], b0, b1);
            MMA(C[2 * np][1], a0[1], a1[1], a2[1], a3[1], b0, b1);
            MMA(C[2 * np + 1][0], a0[0], a1[0], a2[0], a3[0], b2, b3);
            MMA(C[2 * np + 1][1], a0[1], a1[1], a2[1], a3[1], b2, b3);
        }
    }

    // ---- ReLU + layer 3 partials (fp32) ----
    float po[4][3];
#pragma unroll
    for (int r = 0; r < 4; r++)
#pragma unroll
        for (int j = 0; j < 3; j++) po[r][j] = 0.f;
#pragma unroll
    for (int nt = 0; nt < 8; nt++) {
        int col = nt * 8 + lr * 2;
        float wa0 = w3s[col * 3], wa1 = w3s[col * 3 + 1], wa2 = w3s[col * 3 + 2];
        float wb0 = w3s[(col + 1) * 3], wb1 = w3s[(col + 1) * 3 + 1],
              wb2 = w3s[(col + 1) * 3 + 2];
#pragma unroll
        for (int m = 0; m < 2; m++) {
            float h0 = fmaxf(C[nt][m][0], 0.f), h1 = fmaxf(C[nt][m][1], 0.f);
            float h2 = fmaxf(C[nt][m][2], 0.f), h3 = fmaxf(C[nt][m][3], 0.f);
            po[2 * m][0] += h0 * wa0 + h1 * wb0;
            po[2 * m][1] += h0 * wa1 + h1 * wb1;
            po[2 * m][2] += h0 * wa2 + h1 * wb2;
            po[2 * m + 1][0] += h2 * wa0 + h3 * wb0;
            po[2 * m + 1][1] += h2 * wa1 + h3 * wb1;
            po[2 * m + 1][2] += h2 * wa2 + h3 * wb2;
        }
    }
#pragma unroll
    for (int r = 0; r < 4; r++)
#pragma unroll
        for (int j = 0; j < 3; j++) {
            po[r][j] += __shfl_xor_sync(0xffffffffu, po[r][j], 1);
            po[r][j] += __shfl_xor_sync(0xffffffffu, po[r][j], 2);
        }
    int rowsg[4] = {lq, lq + 8, lq + 16, lq + 24};
    int oir[4];
#pragma unroll
    for (int r = 0; r < 4; r++)
        oir[r] = __shfl_sync(0xffffffffu, oi, rowsg[r]);
    if (lr == 0) {
#pragma unroll
        for (int r = 0; r < 4; r++) {
            if (wbase + rowsg[r] < n) {
                size_t off = (size_t)oir[r] * 3;
                out[off] = po[r][0]; out[off + 1] = po[r][1]; out[off + 2] = po[r][2];
            }
        }
    }
}

extern "C" void kernel_launch(void* const* d_in, const int* in_sizes, int n_in,
                              void* d_out, int out_size) {
    const float* x      = (const float*)d_in[0];
    const float* tables = (const float*)d_in[1];
    const float* w1     = (const float*)d_in[2];
    const float* w2     = (const float*)d_in[3];
    const float* w3     = (const float*)d_in[4];
    float* out = (float*)d_out;

    const int n = in_sizes[0] / 2;
    const float2* x2 = (const float2*)x;

    zero_hist_k<<<NBINS / 256, 256>>>();
    hist_k<<<(n + 255) / 256, 256>>>(x2, n);
    scan_k<<<1, 1024>>>();
    scatter_k<<<(n + 255) / 256, 256>>>(x2, n);

    cudaFuncSetAttribute(hashmlp_hmma_kernel,
                         cudaFuncAttributeMaxDynamicSharedMemorySize, SMEM_TOT);
    hashmlp_hmma_kernel<<<(n + 255) / 256, 256, SMEM_TOT>>>(x2, tables, w1, w2,
                                                            w3, out, n);
}